// round 6
// baseline (speedup 1.0000x reference)
#include <cuda_runtime.h>
#include <cuda_bf16.h>
#include <cstdint>
#include <math.h>

// Problem shape (fixed by the reference)
#define BB 4
#define TT 2048
#define CC 1024
#define HH 1024

// ---------------------------------------------------------------------------
// Scratch (__device__ globals; allocation-free per harness rules)
// ---------------------------------------------------------------------------
__device__ __nv_bfloat16 g_xhi[(long)BB * TT * CC];
__device__ __nv_bfloat16 g_xlo[(long)BB * TT * CC];
__device__ __nv_bfloat16 g_wkhi[(long)HH * CC];
__device__ __nv_bfloat16 g_wklo[(long)HH * CC];
__device__ __nv_bfloat16 g_wvhi[(long)HH * CC];
__device__ __nv_bfloat16 g_wvlo[(long)HH * CC];
__device__ float         g_Vf[(long)BB * TT * HH];
__device__ __nv_bfloat16 g_Khi[(long)BB * TT * HH];
__device__ __nv_bfloat16 g_Klo[(long)BB * TT * HH];
__device__ __nv_bfloat16 g_Vthi[(long)BB * HH * TT];   // transposed [b][h][t]
__device__ __nv_bfloat16 g_Vtlo[(long)BB * HH * TT];
__device__ float         g_S[(long)BB * TT * TT];
__device__ __nv_bfloat16 g_Phi[(long)BB * TT * TT];
__device__ __nv_bfloat16 g_Plo[(long)BB * TT * TT];

// ---------------------------------------------------------------------------
// PTX helpers (compute_103-safe: sm_80-era tensor ISA only)
// ---------------------------------------------------------------------------
__device__ __forceinline__ uint32_t smem_u32(const void* p) {
    uint32_t a;
    asm("{ .reg .u64 t; cvta.to.shared.u64 t, %1; cvt.u32.u64 %0, t; }"
        : "=r"(a) : "l"(p));
    return a;
}

__device__ __forceinline__ void cpa16(uint32_t s, const void* g) {
    asm volatile("cp.async.cg.shared.global [%0], [%1], 16;" :: "r"(s), "l"(g));
}
#define CP_COMMIT()  asm volatile("cp.async.commit_group;" ::: "memory")
#define CP_WAIT(n)   asm volatile("cp.async.wait_group %0;" :: "n"(n) : "memory")

#define LDSM4(r0, r1, r2, r3, addr) \
    asm volatile("ldmatrix.sync.aligned.m8n8.x4.shared.b16 {%0,%1,%2,%3}, [%4];" \
                 : "=r"(r0), "=r"(r1), "=r"(r2), "=r"(r3) : "r"(addr))

#define MMA16816(c, a, b0, b1) \
    asm volatile("mma.sync.aligned.m16n8k16.row.col.f32.bf16.bf16.f32 " \
                 "{%0,%1,%2,%3}, {%4,%5,%6,%7}, {%8,%9}, {%0,%1,%2,%3};" \
                 : "+f"((c)[0]), "+f"((c)[1]), "+f"((c)[2]), "+f"((c)[3]) \
                 : "r"((a)[0]), "r"((a)[1]), "r"((a)[2]), "r"((a)[3]), \
                   "r"(b0), "r"(b1))

// ---------------------------------------------------------------------------
// HMMA NT GEMM, bf16x3 split precision, 3-stage cp.async pipeline.
// C[m,n] = scale * sum_k (Ahi+Alo)[m,k]*(Bhi+Blo)[n,k]   (lo*lo dropped)
// CTA tile 128x128, BK=32 halves, 256 thr (8 warps, 4x2), warp tile 32x64.
// SMEM: 3 stages x [Ahi 8K][Alo 8K][Bhi 8K][Blo 8K] = 96KB.
// Rows are 64B (32 bf16); swizzle: 16B-chunk c ^= (row>>1)&3.
// mode: 0 = plain, 1 = causal tile-skip (bn > bm), 2 = k-bounded (PV, bm
//       reversed so longest tiles launch first)
// outMode: 0 = fp32 C (scaled); 1 = bf16 hi/lo split into Chi/Clo
// ---------------------------------------------------------------------------
#define GEMM_SMEM_BYTES (3 * 32768)

__device__ __forceinline__ void load_tiles(
    uint32_t sb, const __nv_bfloat16* __restrict__ Ah,
    const __nv_bfloat16* __restrict__ Al,
    const __nv_bfloat16* __restrict__ Bh,
    const __nv_bfloat16* __restrict__ Bl,
    int K, int aRow0, int bRow0, int kh, int tid)
{
#pragma unroll
    for (int t = 0; t < 2; t++) {
        int idx = tid + t * 256;
        int row = idx >> 2;              // 0..127
        int c   = idx & 3;               // 16B chunk in 64B row
        uint32_t off = (uint32_t)(row << 6) + ((uint32_t)(c ^ ((row >> 1) & 3)) << 4);
        long ga = (long)(aRow0 + row) * K + kh + c * 8;
        long gb = (long)(bRow0 + row) * K + kh + c * 8;
        cpa16(sb + off,         Ah + ga);
        cpa16(sb + 8192 + off,  Al + ga);
        cpa16(sb + 16384 + off, Bh + gb);
        cpa16(sb + 24576 + off, Bl + gb);
    }
}

__global__ void __launch_bounds__(256)
mma_gemm_nt(const __nv_bfloat16* __restrict__ Ahi, const __nv_bfloat16* __restrict__ Alo,
            const __nv_bfloat16* __restrict__ Bhi, const __nv_bfloat16* __restrict__ Blo,
            float* __restrict__ C,
            __nv_bfloat16* __restrict__ Chi, __nv_bfloat16* __restrict__ Clo,
            int M, int N, int K, long sA, long sB, long sC,
            float scale, int mode, int outMode)
{
    int bm = blockIdx.y, bn = blockIdx.x, bz = blockIdx.z;
    if (mode == 1 && bn > bm) return;
    if (mode == 2) bm = gridDim.y - 1 - bm;   // longest-k tiles first

    extern __shared__ __align__(1024) char smem[];
    uint32_t sbase = smem_u32(smem);

    const __nv_bfloat16* Ah = Ahi + (long)bz * sA;
    const __nv_bfloat16* Al = Alo + (long)bz * sA;
    const __nv_bfloat16* Bh = Bhi + (long)bz * sB;
    const __nv_bfloat16* Bl = Blo + (long)bz * sB;

    int tid = threadIdx.x, lane = tid & 31, wid = tid >> 5;
    int wm = wid & 3;                    // 4 warps along M
    int wn = wid >> 2;                   // 2 warps along N

    int kend = (mode == 2) ? min(K, bm * 128 + 128) : K;
    int nch  = kend >> 5;                // BK=32 chunks (always >= 2 here)

    int aRow0 = bm * 128, bRow0 = bn * 128;

    float acc[2][8][4];
#pragma unroll
    for (int i = 0; i < 2; i++)
#pragma unroll
        for (int j = 0; j < 8; j++)
#pragma unroll
            for (int r = 0; r < 4; r++) acc[i][j][r] = 0.0f;

    // ldmatrix lane address components
    int arow_l = wm * 32 + (lane & 15);
    int ac_sel = lane >> 4;                         // 0/1
    int brow_l = wn * 64 + ((lane >> 4) << 3) + (lane & 7);
    int bc_sel = (lane >> 3) & 1;

    // Prologue: stages 0,1
    load_tiles(sbase,         Ah, Al, Bh, Bl, K, aRow0, bRow0, 0,  tid);
    CP_COMMIT();
    load_tiles(sbase + 32768, Ah, Al, Bh, Bl, K, aRow0, bRow0, 32, tid);
    CP_COMMIT();

    uint32_t buf = 0;                    // byte offset of current stage
    for (int i = 0; i < nch; i++) {
        CP_WAIT(1);                      // oldest stage ready
        __syncthreads();                 // also guards WAR on stage (i+2)%3

        if (i + 2 < nch) {
            uint32_t nb = buf + 2 * 32768;
            if (nb >= 3u * 32768) nb -= 3u * 32768;
            load_tiles(sbase + nb, Ah, Al, Bh, Bl, K, aRow0, bRow0, (i + 2) * 32, tid);
        }
        CP_COMMIT();                     // unconditional: keeps group count exact

        uint32_t sb = sbase + buf;
#pragma unroll
        for (int ks = 0; ks < 2; ks++) {
            uint32_t a_hi[2][4], a_lo[2][4];
#pragma unroll
            for (int mt = 0; mt < 2; mt++) {
                int r = arow_l + mt * 16;
                int c = ks * 2 + ac_sel;
                uint32_t off = (uint32_t)(r << 6) + ((uint32_t)(c ^ ((r >> 1) & 3)) << 4);
                LDSM4(a_hi[mt][0], a_hi[mt][1], a_hi[mt][2], a_hi[mt][3], sb + off);
                LDSM4(a_lo[mt][0], a_lo[mt][1], a_lo[mt][2], a_lo[mt][3], sb + 8192 + off);
            }
            uint32_t b_hi[4][4];
#pragma unroll
            for (int g = 0; g < 4; g++) {
                int r = brow_l + g * 16;
                int c = ks * 2 + bc_sel;
                uint32_t off = (uint32_t)(r << 6) + ((uint32_t)(c ^ ((r >> 1) & 3)) << 4);
                LDSM4(b_hi[g][0], b_hi[g][1], b_hi[g][2], b_hi[g][3], sb + 16384 + off);
            }
            // hi*hi while b_lo loads can follow
#pragma unroll
            for (int mt = 0; mt < 2; mt++)
#pragma unroll
                for (int g = 0; g < 4; g++)
#pragma unroll
                    for (int h = 0; h < 2; h++)
                        MMA16816(acc[mt][g * 2 + h], a_hi[mt], b_hi[g][h * 2], b_hi[g][h * 2 + 1]);

            uint32_t b_lo[4][4];
#pragma unroll
            for (int g = 0; g < 4; g++) {
                int r = brow_l + g * 16;
                int c = ks * 2 + bc_sel;
                uint32_t off = (uint32_t)(r << 6) + ((uint32_t)(c ^ ((r >> 1) & 3)) << 4);
                LDSM4(b_lo[g][0], b_lo[g][1], b_lo[g][2], b_lo[g][3], sb + 24576 + off);
            }
#pragma unroll
            for (int mt = 0; mt < 2; mt++)
#pragma unroll
                for (int g = 0; g < 4; g++)
#pragma unroll
                    for (int h = 0; h < 2; h++) {
                        int nt = g * 2 + h;
                        MMA16816(acc[mt][nt], a_hi[mt], b_lo[g][h * 2], b_lo[g][h * 2 + 1]);
                        MMA16816(acc[mt][nt], a_lo[mt], b_hi[g][h * 2], b_hi[g][h * 2 + 1]);
                    }
        }

        buf += 32768;
        if (buf >= 3u * 32768) buf = 0;
    }

    // Epilogue
    int row0 = bm * 128 + wm * 32 + (lane >> 2);
    int col0 = bn * 128 + wn * 64 + (lane & 3) * 2;
    if (outMode == 0) {
        float* Cb = C + (long)bz * sC;
#pragma unroll
        for (int mt = 0; mt < 2; mt++)
#pragma unroll
            for (int nt = 0; nt < 8; nt++) {
                float* p0 = Cb + (long)(row0 + mt * 16) * N + col0 + nt * 8;
                float* p1 = p0 + 8 * N;
                float2 v0 = { acc[mt][nt][0] * scale, acc[mt][nt][1] * scale };
                float2 v1 = { acc[mt][nt][2] * scale, acc[mt][nt][3] * scale };
                *(float2*)p0 = v0;
                *(float2*)p1 = v1;
            }
    } else {
        __nv_bfloat16* Hb = Chi + (long)bz * sC;
        __nv_bfloat16* Lb = Clo + (long)bz * sC;
#pragma unroll
        for (int mt = 0; mt < 2; mt++)
#pragma unroll
            for (int nt = 0; nt < 8; nt++)
#pragma unroll
                for (int hh = 0; hh < 2; hh++) {
                    long o = (long)(row0 + mt * 16 + hh * 8) * N + col0 + nt * 8;
                    float v0 = acc[mt][nt][hh * 2 + 0] * scale;
                    float v1 = acc[mt][nt][hh * 2 + 1] * scale;
                    __nv_bfloat16 h0 = __float2bfloat16(v0);
                    __nv_bfloat16 h1 = __float2bfloat16(v1);
                    *(__nv_bfloat162*)(Hb + o) = __nv_bfloat162(h0, h1);
                    *(__nv_bfloat162*)(Lb + o) =
                        __nv_bfloat162(__float2bfloat16(v0 - __bfloat162float(h0)),
                                       __float2bfloat16(v1 - __bfloat162float(h1)));
                }
    }
}

// ---------------------------------------------------------------------------
// fp32 -> (hi, lo) bf16 split, elementwise (vectorized x4)
// ---------------------------------------------------------------------------
__global__ void __launch_bounds__(256) split_kernel(
    const float* __restrict__ s, __nv_bfloat16* __restrict__ hi,
    __nv_bfloat16* __restrict__ lo, long n)
{
    long i = ((long)blockIdx.x * 256 + threadIdx.x) * 4;
    if (i >= n) return;
    float4 v = *(const float4*)(s + i);
    __nv_bfloat16 h0 = __float2bfloat16(v.x), h1 = __float2bfloat16(v.y);
    __nv_bfloat16 h2 = __float2bfloat16(v.z), h3 = __float2bfloat16(v.w);
    __nv_bfloat162* H = (__nv_bfloat162*)(hi + i);
    H[0] = __nv_bfloat162(h0, h1);
    H[1] = __nv_bfloat162(h2, h3);
    __nv_bfloat162* L = (__nv_bfloat162*)(lo + i);
    L[0] = __nv_bfloat162(__float2bfloat16(v.x - __bfloat162float(h0)),
                          __float2bfloat16(v.y - __bfloat162float(h1)));
    L[1] = __nv_bfloat162(__float2bfloat16(v.z - __bfloat162float(h2)),
                          __float2bfloat16(v.w - __bfloat162float(h3)));
}

// ---------------------------------------------------------------------------
// Per-batch transpose + split: Vf[b][t][h] -> Vt{hi,lo}[b][h][t]
// ---------------------------------------------------------------------------
__global__ void __launch_bounds__(256) transpose_split_kernel(
    const float* __restrict__ src, __nv_bfloat16* __restrict__ dhi,
    __nv_bfloat16* __restrict__ dlo)
{
    __shared__ float tile[32][33];
    int b = blockIdx.z;
    int h0 = blockIdx.x * 32, t0 = blockIdx.y * 32;
    const float* s = src + (long)b * TT * HH;
    int tx = threadIdx.x, ty = threadIdx.y;
#pragma unroll
    for (int i = ty; i < 32; i += 8)
        tile[i][tx] = s[(long)(t0 + i) * HH + h0 + tx];
    __syncthreads();
    __nv_bfloat16* oh = dhi + (long)b * HH * TT;
    __nv_bfloat16* ol = dlo + (long)b * HH * TT;
#pragma unroll
    for (int i = ty; i < 32; i += 8) {
        float v = tile[tx][i];
        __nv_bfloat16 hv = __float2bfloat16(v);
        long o = (long)(h0 + i) * TT + t0 + tx;
        oh[o] = hv;
        ol[o] = __float2bfloat16(v - __bfloat162float(hv));
    }
}

// ---------------------------------------------------------------------------
// Causal softmax over S rows; writes P as bf16 hi/lo (tail zero-filled)
// ---------------------------------------------------------------------------
__global__ void __launch_bounds__(256) softmax_split_kernel(
    float* __restrict__ S, __nv_bfloat16* __restrict__ Phi,
    __nv_bfloat16* __restrict__ Plo)
{
    __shared__ float red[8];
    int r = blockIdx.x;
    int b = r / TT, q = r % TT;
    float* row = S + ((long)b * TT + q) * TT;
    __nv_bfloat16* ph = Phi + ((long)b * TT + q) * TT;
    __nv_bfloat16* pl = Plo + ((long)b * TT + q) * TT;
    int L = q + 1;
    int tid = threadIdx.x, lane = tid & 31, wid = tid >> 5;

    float m = -INFINITY;
    for (int j = tid; j < L; j += 256) m = fmaxf(m, row[j]);
#pragma unroll
    for (int o = 16; o; o >>= 1) m = fmaxf(m, __shfl_xor_sync(0xffffffffu, m, o));
    if (lane == 0) red[wid] = m;
    __syncthreads();
    if (tid == 0) {
        float mx = red[0];
#pragma unroll
        for (int i = 1; i < 8; i++) mx = fmaxf(mx, red[i]);
        red[0] = mx;
    }
    __syncthreads();
    m = red[0];
    __syncthreads();

    float s = 0.0f;
    for (int j = tid; j < L; j += 256) {
        float e = expf(row[j] - m);
        row[j] = e;
        s += e;
    }
#pragma unroll
    for (int o = 16; o; o >>= 1) s += __shfl_xor_sync(0xffffffffu, s, o);
    if (lane == 0) red[wid] = s;
    __syncthreads();
    if (tid == 0) {
        float ss = red[0];
#pragma unroll
        for (int i = 1; i < 8; i++) ss += red[i];
        red[0] = ss;
    }
    __syncthreads();
    float inv = 1.0f / red[0];

    for (int j = tid; j < L; j += 256) {
        float e = row[j] * inv;
        __nv_bfloat16 hv = __float2bfloat16(e);
        ph[j] = hv;
        pl[j] = __float2bfloat16(e - __bfloat162float(hv));
    }
    __nv_bfloat16 z = __float2bfloat16(0.0f);
    for (int j = L + tid; j < TT; j += 256) { ph[j] = z; pl[j] = z; }
}

// ---------------------------------------------------------------------------
// Launch
// ---------------------------------------------------------------------------
extern "C" void kernel_launch(void* const* d_in, const int* in_sizes, int n_in,
                              void* d_out, int out_size)
{
    const float* x  = (const float*)d_in[0];   // [B,T,C]
    const float* Wk = (const float*)d_in[1];   // [H,C]
    const float* Wv = (const float*)d_in[2];   // [H,C]
    float* out = (float*)d_out;                // [B,T,H]

    __nv_bfloat16 *xhi, *xlo, *wkhi, *wklo, *wvhi, *wvlo;
    __nv_bfloat16 *khi, *klo, *vthi, *vtlo, *phi, *plo;
    float *vf, *sp;
    cudaGetSymbolAddress((void**)&xhi,  g_xhi);
    cudaGetSymbolAddress((void**)&xlo,  g_xlo);
    cudaGetSymbolAddress((void**)&wkhi, g_wkhi);
    cudaGetSymbolAddress((void**)&wklo, g_wklo);
    cudaGetSymbolAddress((void**)&wvhi, g_wvhi);
    cudaGetSymbolAddress((void**)&wvlo, g_wvlo);
    cudaGetSymbolAddress((void**)&vf,   g_Vf);
    cudaGetSymbolAddress((void**)&khi,  g_Khi);
    cudaGetSymbolAddress((void**)&klo,  g_Klo);
    cudaGetSymbolAddress((void**)&vthi, g_Vthi);
    cudaGetSymbolAddress((void**)&vtlo, g_Vtlo);
    cudaGetSymbolAddress((void**)&sp,   g_S);
    cudaGetSymbolAddress((void**)&phi,  g_Phi);
    cudaGetSymbolAddress((void**)&plo,  g_Plo);

    cudaFuncSetAttribute(mma_gemm_nt, cudaFuncAttributeMaxDynamicSharedMemorySize,
                         GEMM_SMEM_BYTES);

    const float scale = 1.0f / 32.0f;          // HEAD_SIZE^-0.5

    // 1) split inputs into bf16 hi/lo
    {
        long nx = (long)BB * TT * CC;
        split_kernel<<<(unsigned)(nx / 4 / 256), 256>>>(x, xhi, xlo, nx);
        long nw = (long)HH * CC;
        split_kernel<<<(unsigned)(nw / 4 / 256), 256>>>(Wk, wkhi, wklo, nw);
        split_kernel<<<(unsigned)(nw / 4 / 256), 256>>>(Wv, wvhi, wvlo, nw);
    }

    // 2) projections. K: split written directly from epilogue. V: fp32 (for transpose).
    {
        dim3 grid(HH / 128, (BB * TT) / 128, 1);
        mma_gemm_nt<<<grid, 256, GEMM_SMEM_BYTES>>>(
            xhi, xlo, wkhi, wklo, nullptr, khi, klo,
            BB * TT, HH, CC, 0, 0, 0, 1.0f, 0, 1);
        mma_gemm_nt<<<grid, 256, GEMM_SMEM_BYTES>>>(
            xhi, xlo, wvhi, wvlo, vf, nullptr, nullptr,
            BB * TT, HH, CC, 0, 0, 0, 1.0f, 0, 0);
    }

    // 3) transpose+split V
    {
        dim3 tg(HH / 32, TT / 32, BB);
        transpose_split_kernel<<<tg, dim3(32, 8)>>>(vf, vthi, vtlo);
    }

    // 4) S = scale * K @ K^T (causal lower-triangular tiles only)
    {
        dim3 grid(TT / 128, TT / 128, BB);
        mma_gemm_nt<<<grid, 256, GEMM_SMEM_BYTES>>>(
            khi, klo, khi, klo, sp, nullptr, nullptr,
            TT, TT, HH, (long)TT * HH, (long)TT * HH, (long)TT * TT, scale, 1, 0);
    }

    // 5) causal softmax -> P hi/lo (zero-filled tails)
    softmax_split_kernel<<<BB * TT, 256>>>(sp, phi, plo);

    // 6) out = P @ V  (NT against transposed V, k-loop bounded by causality)
    {
        dim3 grid(HH / 128, TT / 128, BB);
        mma_gemm_nt<<<grid, 256, GEMM_SMEM_BYTES>>>(
            phi, plo, vthi, vtlo, out, nullptr, nullptr,
            TT, HH, TT, (long)TT * TT, (long)HH * TT, (long)TT * HH, 1.0f, 2, 0);
    }
}

// round 7
// speedup vs baseline: 1.0423x; 1.0423x over previous
#include <cuda_runtime.h>
#include <cuda_bf16.h>
#include <cstdint>
#include <math.h>

// Problem shape (fixed by the reference)
#define BB 4
#define TT 2048
#define CC 1024
#define HH 1024

// ---------------------------------------------------------------------------
// Scratch (__device__ globals; allocation-free per harness rules)
// ---------------------------------------------------------------------------
__device__ __nv_bfloat16 g_xhi[(long)BB * TT * CC];
__device__ __nv_bfloat16 g_xlo[(long)BB * TT * CC];
__device__ __nv_bfloat16 g_wkhi[(long)HH * CC];
__device__ __nv_bfloat16 g_wklo[(long)HH * CC];
__device__ __nv_bfloat16 g_wvhi[(long)HH * CC];
__device__ __nv_bfloat16 g_wvlo[(long)HH * CC];
__device__ float         g_Vf[(long)BB * TT * HH];
__device__ __nv_bfloat16 g_Khi[(long)BB * TT * HH];
__device__ __nv_bfloat16 g_Klo[(long)BB * TT * HH];
__device__ __nv_bfloat16 g_Vthi[(long)BB * HH * TT];   // transposed [b][h][t]
__device__ __nv_bfloat16 g_Vtlo[(long)BB * HH * TT];
__device__ float         g_S[(long)BB * TT * TT];
__device__ __nv_bfloat16 g_Phi[(long)BB * TT * TT];
__device__ __nv_bfloat16 g_Plo[(long)BB * TT * TT];

// ---------------------------------------------------------------------------
// PTX helpers (compute_103-safe: sm_80-era tensor ISA only)
// ---------------------------------------------------------------------------
__device__ __forceinline__ uint32_t smem_u32(const void* p) {
    uint32_t a;
    asm("{ .reg .u64 t; cvta.to.shared.u64 t, %1; cvt.u32.u64 %0, t; }"
        : "=r"(a) : "l"(p));
    return a;
}

__device__ __forceinline__ void cpa16(uint32_t s, const void* g) {
    asm volatile("cp.async.cg.shared.global [%0], [%1], 16;" :: "r"(s), "l"(g));
}
#define CP_COMMIT()  asm volatile("cp.async.commit_group;" ::: "memory")
#define CP_WAIT(n)   asm volatile("cp.async.wait_group %0;" :: "n"(n) : "memory")

#define LDSM4(r0, r1, r2, r3, addr) \
    asm volatile("ldmatrix.sync.aligned.m8n8.x4.shared.b16 {%0,%1,%2,%3}, [%4];" \
                 : "=r"(r0), "=r"(r1), "=r"(r2), "=r"(r3) : "r"(addr))

#define MMA16816(c, a, b0, b1) \
    asm volatile("mma.sync.aligned.m16n8k16.row.col.f32.bf16.bf16.f32 " \
                 "{%0,%1,%2,%3}, {%4,%5,%6,%7}, {%8,%9}, {%0,%1,%2,%3};" \
                 : "+f"((c)[0]), "+f"((c)[1]), "+f"((c)[2]), "+f"((c)[3]) \
                 : "r"((a)[0]), "r"((a)[1]), "r"((a)[2]), "r"((a)[3]), \
                   "r"(b0), "r"(b1))

// ---------------------------------------------------------------------------
// HMMA NT GEMM, bf16x3 split precision, 3-stage cp.async pipeline.
// C[m,n] = scale * sum_k (Ahi+Alo)[m,k]*(Bhi+Blo)[n,k]   (lo*lo dropped)
// CTA tile 128x128, BK=32 halves, 256 thr (8 warps, 4x2), warp tile 32x64.
// SMEM: 3 stages x [Ahi 8K][Alo 8K][Bhi 8K][Blo 8K] = 96KB.
// __launch_bounds__(256, 2): pins regs <= 128 so 2 CTAs/SM stay resident
// (129 regs in R5 silently halved occupancy -> tensor 51%).
// mode: 0 = plain, 1 = causal tile-skip (bn > bm), 2 = k-bounded (PV, bm
//       reversed so longest tiles launch first)
// outMode: 0 = fp32 C (scaled); 1 = bf16 hi/lo split into Chi/Clo
// ---------------------------------------------------------------------------
#define GEMM_SMEM_BYTES (3 * 32768)

__device__ __forceinline__ void load_tiles(
    uint32_t sb, const __nv_bfloat16* __restrict__ Ah,
    const __nv_bfloat16* __restrict__ Al,
    const __nv_bfloat16* __restrict__ Bh,
    const __nv_bfloat16* __restrict__ Bl,
    int K, int aRow0, int bRow0, int kh, int tid)
{
#pragma unroll
    for (int t = 0; t < 2; t++) {
        int idx = tid + t * 256;
        int row = idx >> 2;              // 0..127
        int c   = idx & 3;               // 16B chunk in 64B row
        uint32_t off = (uint32_t)(row << 6) + ((uint32_t)(c ^ ((row >> 1) & 3)) << 4);
        long ga = (long)(aRow0 + row) * K + kh + c * 8;
        long gb = (long)(bRow0 + row) * K + kh + c * 8;
        cpa16(sb + off,         Ah + ga);
        cpa16(sb + 8192 + off,  Al + ga);
        cpa16(sb + 16384 + off, Bh + gb);
        cpa16(sb + 24576 + off, Bl + gb);
    }
}

__global__ void __launch_bounds__(256, 2)
mma_gemm_nt(const __nv_bfloat16* __restrict__ Ahi, const __nv_bfloat16* __restrict__ Alo,
            const __nv_bfloat16* __restrict__ Bhi, const __nv_bfloat16* __restrict__ Blo,
            float* __restrict__ C,
            __nv_bfloat16* __restrict__ Chi, __nv_bfloat16* __restrict__ Clo,
            int M, int N, int K, long sA, long sB, long sC,
            float scale, int mode, int outMode)
{
    int bm = blockIdx.y, bn = blockIdx.x, bz = blockIdx.z;
    if (mode == 1 && bn > bm) return;
    if (mode == 2) bm = gridDim.y - 1 - bm;   // longest-k tiles first

    extern __shared__ __align__(1024) char smem[];
    uint32_t sbase = smem_u32(smem);

    const __nv_bfloat16* Ah = Ahi + (long)bz * sA;
    const __nv_bfloat16* Al = Alo + (long)bz * sA;
    const __nv_bfloat16* Bh = Bhi + (long)bz * sB;
    const __nv_bfloat16* Bl = Blo + (long)bz * sB;

    int tid = threadIdx.x, lane = tid & 31, wid = tid >> 5;
    int wm = wid & 3;                    // 4 warps along M
    int wn = wid >> 2;                   // 2 warps along N

    int kend = (mode == 2) ? min(K, bm * 128 + 128) : K;
    int nch  = kend >> 5;                // BK=32 chunks (always >= 2 here)

    int aRow0 = bm * 128, bRow0 = bn * 128;

    float acc[2][8][4];
#pragma unroll
    for (int i = 0; i < 2; i++)
#pragma unroll
        for (int j = 0; j < 8; j++)
#pragma unroll
            for (int r = 0; r < 4; r++) acc[i][j][r] = 0.0f;

    // ldmatrix lane address components
    int arow_l = wm * 32 + (lane & 15);
    int ac_sel = lane >> 4;                         // 0/1
    int brow_l = wn * 64 + ((lane >> 4) << 3) + (lane & 7);
    int bc_sel = (lane >> 3) & 1;

    // Prologue: stages 0,1
    load_tiles(sbase,         Ah, Al, Bh, Bl, K, aRow0, bRow0, 0,  tid);
    CP_COMMIT();
    load_tiles(sbase + 32768, Ah, Al, Bh, Bl, K, aRow0, bRow0, 32, tid);
    CP_COMMIT();

    uint32_t buf = 0;                    // byte offset of current stage
    for (int i = 0; i < nch; i++) {
        CP_WAIT(1);                      // oldest stage ready
        __syncthreads();                 // also guards WAR on stage (i+2)%3

        if (i + 2 < nch) {
            uint32_t nb = buf + 2 * 32768;
            if (nb >= 3u * 32768) nb -= 3u * 32768;
            load_tiles(sbase + nb, Ah, Al, Bh, Bl, K, aRow0, bRow0, (i + 2) * 32, tid);
        }
        CP_COMMIT();                     // unconditional: keeps group count exact

        uint32_t sb = sbase + buf;
#pragma unroll
        for (int ks = 0; ks < 2; ks++) {
            uint32_t a_hi[2][4], a_lo[2][4];
#pragma unroll
            for (int mt = 0; mt < 2; mt++) {
                int r = arow_l + mt * 16;
                int c = ks * 2 + ac_sel;
                uint32_t off = (uint32_t)(r << 6) + ((uint32_t)(c ^ ((r >> 1) & 3)) << 4);
                LDSM4(a_hi[mt][0], a_hi[mt][1], a_hi[mt][2], a_hi[mt][3], sb + off);
                LDSM4(a_lo[mt][0], a_lo[mt][1], a_lo[mt][2], a_lo[mt][3], sb + 8192 + off);
            }
            uint32_t b_hi[4][4];
#pragma unroll
            for (int g = 0; g < 4; g++) {
                int r = brow_l + g * 16;
                int c = ks * 2 + bc_sel;
                uint32_t off = (uint32_t)(r << 6) + ((uint32_t)(c ^ ((r >> 1) & 3)) << 4);
                LDSM4(b_hi[g][0], b_hi[g][1], b_hi[g][2], b_hi[g][3], sb + 16384 + off);
            }
            // hi*hi while b_lo loads can follow
#pragma unroll
            for (int mt = 0; mt < 2; mt++)
#pragma unroll
                for (int g = 0; g < 4; g++)
#pragma unroll
                    for (int h = 0; h < 2; h++)
                        MMA16816(acc[mt][g * 2 + h], a_hi[mt], b_hi[g][h * 2], b_hi[g][h * 2 + 1]);

            uint32_t b_lo[4][4];
#pragma unroll
            for (int g = 0; g < 4; g++) {
                int r = brow_l + g * 16;
                int c = ks * 2 + bc_sel;
                uint32_t off = (uint32_t)(r << 6) + ((uint32_t)(c ^ ((r >> 1) & 3)) << 4);
                LDSM4(b_lo[g][0], b_lo[g][1], b_lo[g][2], b_lo[g][3], sb + 24576 + off);
            }
#pragma unroll
            for (int mt = 0; mt < 2; mt++)
#pragma unroll
                for (int g = 0; g < 4; g++)
#pragma unroll
                    for (int h = 0; h < 2; h++) {
                        int nt = g * 2 + h;
                        MMA16816(acc[mt][nt], a_hi[mt], b_lo[g][h * 2], b_lo[g][h * 2 + 1]);
                        MMA16816(acc[mt][nt], a_lo[mt], b_hi[g][h * 2], b_hi[g][h * 2 + 1]);
                    }
        }

        buf += 32768;
        if (buf >= 3u * 32768) buf = 0;
    }

    // Epilogue
    int row0 = bm * 128 + wm * 32 + (lane >> 2);
    int col0 = bn * 128 + wn * 64 + (lane & 3) * 2;
    if (outMode == 0) {
        float* Cb = C + (long)bz * sC;
#pragma unroll
        for (int mt = 0; mt < 2; mt++)
#pragma unroll
            for (int nt = 0; nt < 8; nt++) {
                float* p0 = Cb + (long)(row0 + mt * 16) * N + col0 + nt * 8;
                float* p1 = p0 + 8 * N;
                float2 v0 = { acc[mt][nt][0] * scale, acc[mt][nt][1] * scale };
                float2 v1 = { acc[mt][nt][2] * scale, acc[mt][nt][3] * scale };
                *(float2*)p0 = v0;
                *(float2*)p1 = v1;
            }
    } else {
        __nv_bfloat16* Hb = Chi + (long)bz * sC;
        __nv_bfloat16* Lb = Clo + (long)bz * sC;
#pragma unroll
        for (int mt = 0; mt < 2; mt++)
#pragma unroll
            for (int nt = 0; nt < 8; nt++)
#pragma unroll
                for (int hh = 0; hh < 2; hh++) {
                    long o = (long)(row0 + mt * 16 + hh * 8) * N + col0 + nt * 8;
                    float v0 = acc[mt][nt][hh * 2 + 0] * scale;
                    float v1 = acc[mt][nt][hh * 2 + 1] * scale;
                    __nv_bfloat16 h0 = __float2bfloat16(v0);
                    __nv_bfloat16 h1 = __float2bfloat16(v1);
                    *(__nv_bfloat162*)(Hb + o) = __nv_bfloat162(h0, h1);
                    *(__nv_bfloat162*)(Lb + o) =
                        __nv_bfloat162(__float2bfloat16(v0 - __bfloat162float(h0)),
                                       __float2bfloat16(v1 - __bfloat162float(h1)));
                }
    }
}

// ---------------------------------------------------------------------------
// fp32 -> (hi, lo) bf16 split, elementwise (vectorized x4)
// ---------------------------------------------------------------------------
__global__ void __launch_bounds__(256) split_kernel(
    const float* __restrict__ s, __nv_bfloat16* __restrict__ hi,
    __nv_bfloat16* __restrict__ lo, long n)
{
    long i = ((long)blockIdx.x * 256 + threadIdx.x) * 4;
    if (i >= n) return;
    float4 v = *(const float4*)(s + i);
    __nv_bfloat16 h0 = __float2bfloat16(v.x), h1 = __float2bfloat16(v.y);
    __nv_bfloat16 h2 = __float2bfloat16(v.z), h3 = __float2bfloat16(v.w);
    __nv_bfloat162* H = (__nv_bfloat162*)(hi + i);
    H[0] = __nv_bfloat162(h0, h1);
    H[1] = __nv_bfloat162(h2, h3);
    __nv_bfloat162* L = (__nv_bfloat162*)(lo + i);
    L[0] = __nv_bfloat162(__float2bfloat16(v.x - __bfloat162float(h0)),
                          __float2bfloat16(v.y - __bfloat162float(h1)));
    L[1] = __nv_bfloat162(__float2bfloat16(v.z - __bfloat162float(h2)),
                          __float2bfloat16(v.w - __bfloat162float(h3)));
}

// ---------------------------------------------------------------------------
// Per-batch transpose + split: Vf[b][t][h] -> Vt{hi,lo}[b][h][t]
// ---------------------------------------------------------------------------
__global__ void __launch_bounds__(256) transpose_split_kernel(
    const float* __restrict__ src, __nv_bfloat16* __restrict__ dhi,
    __nv_bfloat16* __restrict__ dlo)
{
    __shared__ float tile[32][33];
    int b = blockIdx.z;
    int h0 = blockIdx.x * 32, t0 = blockIdx.y * 32;
    const float* s = src + (long)b * TT * HH;
    int tx = threadIdx.x, ty = threadIdx.y;
#pragma unroll
    for (int i = ty; i < 32; i += 8)
        tile[i][tx] = s[(long)(t0 + i) * HH + h0 + tx];
    __syncthreads();
    __nv_bfloat16* oh = dhi + (long)b * HH * TT;
    __nv_bfloat16* ol = dlo + (long)b * HH * TT;
#pragma unroll
    for (int i = ty; i < 32; i += 8) {
        float v = tile[tx][i];
        __nv_bfloat16 hv = __float2bfloat16(v);
        long o = (long)(h0 + i) * TT + t0 + tx;
        oh[o] = hv;
        ol[o] = __float2bfloat16(v - __bfloat162float(hv));
    }
}

// ---------------------------------------------------------------------------
// Causal softmax over S rows; writes P as bf16 hi/lo (tail zero-filled)
// ---------------------------------------------------------------------------
__global__ void __launch_bounds__(256) softmax_split_kernel(
    float* __restrict__ S, __nv_bfloat16* __restrict__ Phi,
    __nv_bfloat16* __restrict__ Plo)
{
    __shared__ float red[8];
    int r = blockIdx.x;
    int b = r / TT, q = r % TT;
    float* row = S + ((long)b * TT + q) * TT;
    __nv_bfloat16* ph = Phi + ((long)b * TT + q) * TT;
    __nv_bfloat16* pl = Plo + ((long)b * TT + q) * TT;
    int L = q + 1;
    int tid = threadIdx.x, lane = tid & 31, wid = tid >> 5;

    float m = -INFINITY;
    for (int j = tid; j < L; j += 256) m = fmaxf(m, row[j]);
#pragma unroll
    for (int o = 16; o; o >>= 1) m = fmaxf(m, __shfl_xor_sync(0xffffffffu, m, o));
    if (lane == 0) red[wid] = m;
    __syncthreads();
    if (tid == 0) {
        float mx = red[0];
#pragma unroll
        for (int i = 1; i < 8; i++) mx = fmaxf(mx, red[i]);
        red[0] = mx;
    }
    __syncthreads();
    m = red[0];
    __syncthreads();

    float s = 0.0f;
    for (int j = tid; j < L; j += 256) {
        float e = expf(row[j] - m);
        row[j] = e;
        s += e;
    }
#pragma unroll
    for (int o = 16; o; o >>= 1) s += __shfl_xor_sync(0xffffffffu, s, o);
    if (lane == 0) red[wid] = s;
    __syncthreads();
    if (tid == 0) {
        float ss = red[0];
#pragma unroll
        for (int i = 1; i < 8; i++) ss += red[i];
        red[0] = ss;
    }
    __syncthreads();
    float inv = 1.0f / red[0];

    for (int j = tid; j < L; j += 256) {
        float e = row[j] * inv;
        __nv_bfloat16 hv = __float2bfloat16(e);
        ph[j] = hv;
        pl[j] = __float2bfloat16(e - __bfloat162float(hv));
    }
    __nv_bfloat16 z = __float2bfloat16(0.0f);
    for (int j = L + tid; j < TT; j += 256) { ph[j] = z; pl[j] = z; }
}

// ---------------------------------------------------------------------------
// Launch
// ---------------------------------------------------------------------------
extern "C" void kernel_launch(void* const* d_in, const int* in_sizes, int n_in,
                              void* d_out, int out_size)
{
    const float* x  = (const float*)d_in[0];   // [B,T,C]
    const float* Wk = (const float*)d_in[1];   // [H,C]
    const float* Wv = (const float*)d_in[2];   // [H,C]
    float* out = (float*)d_out;                // [B,T,H]

    __nv_bfloat16 *xhi, *xlo, *wkhi, *wklo, *wvhi, *wvlo;
    __nv_bfloat16 *khi, *klo, *vthi, *vtlo, *phi, *plo;
    float *vf, *sp;
    cudaGetSymbolAddress((void**)&xhi,  g_xhi);
    cudaGetSymbolAddress((void**)&xlo,  g_xlo);
    cudaGetSymbolAddress((void**)&wkhi, g_wkhi);
    cudaGetSymbolAddress((void**)&wklo, g_wklo);
    cudaGetSymbolAddress((void**)&wvhi, g_wvhi);
    cudaGetSymbolAddress((void**)&wvlo, g_wvlo);
    cudaGetSymbolAddress((void**)&vf,   g_Vf);
    cudaGetSymbolAddress((void**)&khi,  g_Khi);
    cudaGetSymbolAddress((void**)&klo,  g_Klo);
    cudaGetSymbolAddress((void**)&vthi, g_Vthi);
    cudaGetSymbolAddress((void**)&vtlo, g_Vtlo);
    cudaGetSymbolAddress((void**)&sp,   g_S);
    cudaGetSymbolAddress((void**)&phi,  g_Phi);
    cudaGetSymbolAddress((void**)&plo,  g_Plo);

    cudaFuncSetAttribute(mma_gemm_nt, cudaFuncAttributeMaxDynamicSharedMemorySize,
                         GEMM_SMEM_BYTES);

    const float scale = 1.0f / 32.0f;          // HEAD_SIZE^-0.5

    // 1) split inputs into bf16 hi/lo
    {
        long nx = (long)BB * TT * CC;
        split_kernel<<<(unsigned)(nx / 4 / 256), 256>>>(x, xhi, xlo, nx);
        long nw = (long)HH * CC;
        split_kernel<<<(unsigned)(nw / 4 / 256), 256>>>(Wk, wkhi, wklo, nw);
        split_kernel<<<(unsigned)(nw / 4 / 256), 256>>>(Wv, wvhi, wvlo, nw);
    }

    // 2) projections. K: split written directly from epilogue. V: fp32 (for transpose).
    {
        dim3 grid(HH / 128, (BB * TT) / 128, 1);
        mma_gemm_nt<<<grid, 256, GEMM_SMEM_BYTES>>>(
            xhi, xlo, wkhi, wklo, nullptr, khi, klo,
            BB * TT, HH, CC, 0, 0, 0, 1.0f, 0, 1);
        mma_gemm_nt<<<grid, 256, GEMM_SMEM_BYTES>>>(
            xhi, xlo, wvhi, wvlo, vf, nullptr, nullptr,
            BB * TT, HH, CC, 0, 0, 0, 1.0f, 0, 0);
    }

    // 3) transpose+split V
    {
        dim3 tg(HH / 32, TT / 32, BB);
        transpose_split_kernel<<<tg, dim3(32, 8)>>>(vf, vthi, vtlo);
    }

    // 4) S = scale * K @ K^T (causal lower-triangular tiles only)
    {
        dim3 grid(TT / 128, TT / 128, BB);
        mma_gemm_nt<<<grid, 256, GEMM_SMEM_BYTES>>>(
            khi, klo, khi, klo, sp, nullptr, nullptr,
            TT, TT, HH, (long)TT * HH, (long)TT * HH, (long)TT * TT, scale, 1, 0);
    }

    // 5) causal softmax -> P hi/lo (zero-filled tails)
    softmax_split_kernel<<<BB * TT, 256>>>(sp, phi, plo);

    // 6) out = P @ V  (NT against transposed V, k-loop bounded by causality)
    {
        dim3 grid(HH / 128, TT / 128, BB);
        mma_gemm_nt<<<grid, 256, GEMM_SMEM_BYTES>>>(
            phi, plo, vthi, vtlo, out, nullptr, nullptr,
            TT, HH, TT, (long)TT * TT, (long)HH * TT, (long)TT * HH, 1.0f, 2, 0);
    }
}